// round 3
// baseline (speedup 1.0000x reference)
#include <cuda_runtime.h>
#include <cstdint>
#include <math.h>

#define H 128
#define DEG 32
#define TOPK 10
#define NPAD 150016   // 150000 padded to multiple of 64
#define RPAD 512

// ---------------- scratch (device globals; no allocation allowed) ------------
__device__ float d_M[H * H];        // W @ neigh_w
__device__ float d_Mr[H * H];       // W_r @ neigh_w
__device__ float d_w1[H];           // W @ a1
__device__ float d_w2[H];           // W @ a2
__device__ float d_w3[H];           // W_r @ a3
__device__ float d_srel[RPAD];      // rel_emb . w3
__device__ float d_grel[RPAD * H];  // rel_emb @ Mr
__device__ float d_g[(size_t)NPAD * H];  // ent_emb @ M
__device__ float d_ssrc[NPAD];
__device__ float d_sdst[NPAD];

// ---------------- packed f32x2 helpers (FFMA2 only reachable via PTX) --------
__device__ __forceinline__ unsigned long long pack2(float x, float y) {
    unsigned long long v;
    asm("mov.b64 %0, {%1, %2};" : "=l"(v) : "f"(x), "f"(y));
    return v;
}
__device__ __forceinline__ void ffma2(unsigned long long& d,
                                      unsigned long long a,
                                      unsigned long long b) {
    asm("fma.rn.f32x2 %0, %1, %2, %0;" : "+l"(d) : "l"(a), "l"(b));
}
__device__ __forceinline__ float2 unpack2(unsigned long long v) {
    float2 r;
    asm("mov.b64 {%0, %1}, %2;" : "=f"(r.x), "=f"(r.y) : "l"(v));
    return r;
}

// ---------------- prep1: fold weight matrices --------------------------------
// grid 128, block 128. Block r computes row r of M and Mr, plus w1/w2/w3[r].
__global__ void prep1_kernel(const float* __restrict__ W,
                             const float* __restrict__ Wr,
                             const float* __restrict__ a,
                             const float* __restrict__ NW) {
    int r = blockIdx.x;
    int c = threadIdx.x;
    float m = 0.f, mr = 0.f;
#pragma unroll 8
    for (int k = 0; k < H; k++) {
        float nw = NW[k * H + c];
        m  += W[r * H + k] * nw;
        mr += Wr[r * H + k] * nw;
    }
    d_M[r * H + c] = m;
    d_Mr[r * H + c] = mr;
    if (c == 0) {
        float s1 = 0.f, s2 = 0.f, s3 = 0.f;
        for (int j = 0; j < H; j++) {
            s1 += W[r * H + j] * a[j];
            s2 += W[r * H + j] * a[H + j];
            s3 += Wr[r * H + j] * a[2 * H + j];
        }
        d_w1[r] = s1;
        d_w2[r] = s2;
        d_w3[r] = s3;
    }
}

// ---------------- prep2: relation tables -------------------------------------
// grid nRel, block 128.
__global__ void prep2_kernel(const float* __restrict__ rel_emb) {
    int r = blockIdx.x;
    int c = threadIdx.x;
    __shared__ float re[H];
    re[c] = rel_emb[r * H + c];
    __syncthreads();
    float acc = 0.f;
#pragma unroll 8
    for (int k = 0; k < H; k++) acc += re[k] * d_Mr[k * H + c];
    d_grel[r * H + c] = acc;
    if (c == 0) {
        float s = 0.f;
        for (int i = 0; i < H; i++) s += re[i] * d_w3[i];
        d_srel[r] = s;
    }
}

// ---------------- main GEMM: g = ent_emb @ M (+ s_src, s_dst) ----------------
// 256 threads, 64-row tile x 128 cols. warp w handles rows [8w,8w+8), all cols.
// Thread: 4 row-pairs x 4 cols via packed fma.rn.f32x2.
#define TM 64
__global__ __launch_bounds__(256) void gemm_kernel(const float* __restrict__ E,
                                                   int nRows) {
    __shared__ float As[16][68];   // [kk][row], padded
    __shared__ float Bs[16][128];  // [kk][col]
    __shared__ float w1s[H], w2s[H];

    int t = threadIdx.x;
    int lane = t & 31;   // col group: cols [4*lane, 4*lane+4)
    int rg = t >> 5;     // warp id: rows [8*rg, 8*rg+8)
    int row0 = blockIdx.x * TM;

    if (t < H) { w1s[t] = d_w1[t]; w2s[t] = d_w2[t]; }

    unsigned long long acc[4][4];
#pragma unroll
    for (int p = 0; p < 4; p++)
#pragma unroll
        for (int c = 0; c < 4; c++) acc[p][c] = 0ull;

    float sA = 0.f, sB = 0.f;  // s_src / s_dst partials (threads t < 64)

    for (int k0 = 0; k0 < H; k0 += 16) {
        __syncthreads();
        // load A chunk: 64 rows x 16 k
        {
            int r = t >> 2;
            int kq = (t & 3) * 4;
            int rm = row0 + r;
            if (rm > nRows - 1) rm = nRows - 1;
            float4 v = *(const float4*)&E[(size_t)rm * H + k0 + kq];
            As[kq + 0][r] = v.x;
            As[kq + 1][r] = v.y;
            As[kq + 2][r] = v.z;
            As[kq + 3][r] = v.w;
        }
        // load B chunk: 16 k x 128 cols
#pragma unroll
        for (int rep = 0; rep < 2; rep++) {
            int i = t + rep * 256;
            int kk = i >> 5;
            int c4 = (i & 31) * 4;
            *(float4*)&Bs[kk][c4] = *(const float4*)&d_M[(k0 + kk) * H + c4];
        }
        __syncthreads();

#pragma unroll
        for (int kk = 0; kk < 16; kk++) {
            const float* arow = &As[kk][rg * 8];
            unsigned long long ap[4];
#pragma unroll
            for (int p = 0; p < 4; p++) {
                float2 t2 = *(const float2*)(arow + 2 * p);
                ap[p] = pack2(t2.x, t2.y);
            }
            float4 b = *(const float4*)&Bs[kk][lane * 4];
            unsigned long long b0 = pack2(b.x, b.x);
            unsigned long long b1 = pack2(b.y, b.y);
            unsigned long long b2 = pack2(b.z, b.z);
            unsigned long long b3 = pack2(b.w, b.w);
#pragma unroll
            for (int p = 0; p < 4; p++) {
                ffma2(acc[p][0], ap[p], b0);
                ffma2(acc[p][1], ap[p], b1);
                ffma2(acc[p][2], ap[p], b2);
                ffma2(acc[p][3], ap[p], b3);
            }
        }
        // score-path dot products (one thread per row of the tile)
        if (t < TM) {
#pragma unroll
            for (int kk = 0; kk < 16; kk++) {
                float av = As[kk][t];
                sA += av * w1s[k0 + kk];
                sB += av * w2s[k0 + kk];
            }
        }
    }

    // store g (padded scratch; no guard needed)
#pragma unroll
    for (int p = 0; p < 4; p++) {
        float2 c0 = unpack2(acc[p][0]);
        float2 c1 = unpack2(acc[p][1]);
        float2 c2 = unpack2(acc[p][2]);
        float2 c3 = unpack2(acc[p][3]);
        size_t r = (size_t)row0 + rg * 8 + 2 * p;
        float4 lo = make_float4(c0.x, c1.x, c2.x, c3.x);
        float4 hi = make_float4(c0.y, c1.y, c2.y, c3.y);
        *(float4*)&d_g[r * H + lane * 4] = lo;
        *(float4*)&d_g[(r + 1) * H + lane * 4] = hi;
    }
    if (t < TM) {
        d_ssrc[row0 + t] = sA;
        d_sdst[row0 + t] = sB;
    }
}

// ---------------- attention: score, top-k, softmax, gather, tanh -------------
// one warp per entity; lane d owns candidate d (DEG == 32).
__global__ __launch_bounds__(256) void attn_kernel(const int* __restrict__ src,
                                                   const int* __restrict__ rel,
                                                   float* __restrict__ out,
                                                   int nEnt) {
    int gwarp = (blockIdx.x * blockDim.x + threadIdx.x) >> 5;
    int lane = threadIdx.x & 31;
    if (gwarp >= nEnt) return;
    int n = gwarp;

    int s = src[(size_t)n * DEG + lane];
    int r = rel[(size_t)n * DEG + lane];
    float sc = d_ssrc[s] + d_sdst[n] + d_srel[r];
    sc = sc >= 0.f ? sc : 0.2f * sc;  // leaky_relu(0.2)

    // iterative top-10 (ties -> lowest lane, matching lax.top_k)
    int sel_lane[TOPK];
    float sel_e[TOPK];
    float cur = sc;
#pragma unroll
    for (int k = 0; k < TOPK; k++) {
        float bv = cur;
        int bl = lane;
#pragma unroll
        for (int o = 16; o > 0; o >>= 1) {
            float ov = __shfl_xor_sync(0xffffffffu, bv, o);
            int ol = __shfl_xor_sync(0xffffffffu, bl, o);
            if (ov > bv || (ov == bv && ol < bl)) { bv = ov; bl = ol; }
        }
        sel_lane[k] = bl;
        sel_e[k] = bv;
        if (lane == bl) cur = -INFINITY;
    }

    // softmax over the 10 selected scores (sel_e[0] is the max)
    float m = sel_e[0];
    float w[TOPK];
    float denom = 0.f;
#pragma unroll
    for (int k = 0; k < TOPK; k++) {
        w[k] = expf(sel_e[k] - m);
        denom += w[k];
    }
    float inv = 1.0f / denom;

    // gather + weighted sum: lane owns 4 feature channels
    float4 acc = make_float4(0.f, 0.f, 0.f, 0.f);
#pragma unroll
    for (int k = 0; k < TOPK; k++) {
        int sl = sel_lane[k];
        int sk = __shfl_sync(0xffffffffu, s, sl);
        int rk = __shfl_sync(0xffffffffu, r, sl);
        float wk = w[k] * inv;
        float4 gv = *(const float4*)&d_g[(size_t)sk * H + lane * 4];
        float4 rv = *(const float4*)&d_grel[(size_t)rk * H + lane * 4];
        acc.x += wk * (gv.x + rv.x);
        acc.y += wk * (gv.y + rv.y);
        acc.z += wk * (gv.z + rv.z);
        acc.w += wk * (gv.w + rv.w);
    }
    float4 o4 = make_float4(tanhf(acc.x), tanhf(acc.y), tanhf(acc.z), tanhf(acc.w));
    *(float4*)&out[(size_t)n * H + lane * 4] = o4;
}

// ---------------- launch -----------------------------------------------------
extern "C" void kernel_launch(void* const* d_in, const int* in_sizes, int n_in,
                              void* d_out, int out_size) {
    const float* ent = (const float*)d_in[0];   // [N, H]
    const float* rel = (const float*)d_in[1];   // [R, H]
    const float* W   = (const float*)d_in[2];   // [H, H]
    const float* Wr  = (const float*)d_in[3];   // [H, H]
    const float* a   = (const float*)d_in[4];   // [3H, 1]
    const float* NW  = (const float*)d_in[5];   // [H, H]
    const int* src   = (const int*)d_in[6];     // [N, DEG]
    const int* relid = (const int*)d_in[7];     // [N, DEG]
    float* out = (float*)d_out;                 // [N, H]

    int nEnt = in_sizes[0] / H;
    int nRel = in_sizes[1] / H;

    prep1_kernel<<<H, H>>>(W, Wr, a, NW);
    prep2_kernel<<<nRel, H>>>(rel);
    gemm_kernel<<<(nEnt + TM - 1) / TM, 256>>>(ent, nEnt);
    attn_kernel<<<((size_t)nEnt * 32 + 255) / 256, 256>>>(src, relid, out, nEnt);
}

// round 7
// speedup vs baseline: 1.1438x; 1.1438x over previous
#include <cuda_runtime.h>
#include <cstdint>
#include <math.h>

#define H 128
#define DEG 32
#define TOPK 10
#define NPAD 150016   // 150000 padded to multiple of 64
#define RPAD 512

// ---------------- scratch (device globals; no allocation allowed) ------------
__device__ float d_M[H * H];        // W @ neigh_w
__device__ float d_Mr[H * H];       // W_r @ neigh_w
__device__ float d_w1[H];           // W @ a1
__device__ float d_w2[H];           // W @ a2
__device__ float d_w3[H];           // W_r @ a3
__device__ float d_srel[RPAD];      // rel_emb . w3
__device__ float d_grel[RPAD * H];  // rel_emb @ Mr
__device__ float d_g[(size_t)NPAD * H];  // ent_emb @ M
__device__ float d_ssrc[NPAD];
__device__ float d_sdst[NPAD];

// ---------------- packed f32x2 helpers (FFMA2 only reachable via PTX) --------
__device__ __forceinline__ unsigned long long pack2(float x, float y) {
    unsigned long long v;
    asm("mov.b64 %0, {%1, %2};" : "=l"(v) : "f"(x), "f"(y));
    return v;
}
__device__ __forceinline__ void ffma2(unsigned long long& d,
                                      unsigned long long a,
                                      unsigned long long b) {
    asm("fma.rn.f32x2 %0, %1, %2, %0;" : "+l"(d) : "l"(a), "l"(b));
}
__device__ __forceinline__ float2 unpack2(unsigned long long v) {
    float2 r;
    asm("mov.b64 {%0, %1}, %2;" : "=f"(r.x), "=f"(r.y) : "l"(v));
    return r;
}

// ---------------- prep1: fold weight matrices --------------------------------
__global__ void prep1_kernel(const float* __restrict__ W,
                             const float* __restrict__ Wr,
                             const float* __restrict__ a,
                             const float* __restrict__ NW) {
    int r = blockIdx.x;
    int c = threadIdx.x;
    float m = 0.f, mr = 0.f;
#pragma unroll 8
    for (int k = 0; k < H; k++) {
        float nw = NW[k * H + c];
        m  += W[r * H + k] * nw;
        mr += Wr[r * H + k] * nw;
    }
    d_M[r * H + c] = m;
    d_Mr[r * H + c] = mr;
    if (c == 0) {
        float s1 = 0.f, s2 = 0.f, s3 = 0.f;
        for (int j = 0; j < H; j++) {
            s1 += W[r * H + j] * a[j];
            s2 += W[r * H + j] * a[H + j];
            s3 += Wr[r * H + j] * a[2 * H + j];
        }
        d_w1[r] = s1;
        d_w2[r] = s2;
        d_w3[r] = s3;
    }
}

// ---------------- prep2: relation tables -------------------------------------
__global__ void prep2_kernel(const float* __restrict__ rel_emb) {
    int r = blockIdx.x;
    int c = threadIdx.x;
    __shared__ float re[H];
    re[c] = rel_emb[r * H + c];
    __syncthreads();
    float acc = 0.f;
#pragma unroll 8
    for (int k = 0; k < H; k++) acc += re[k] * d_Mr[k * H + c];
    d_grel[r * H + c] = acc;
    if (c == 0) {
        float s = 0.f;
        for (int i = 0; i < H; i++) s += re[i] * d_w3[i];
        d_srel[r] = s;
    }
}

// ---------------- main GEMM: g = ent_emb @ M (+ s_src, s_dst) ----------------
// 256 threads, 64-row tile x 128 cols, K-chunk = 32.
// warp w handles rows [8w,8w+8); thread: 4 row-pairs x 4 cols via fma.rn.f32x2.
#define TM 64
#define KC 32
__global__ __launch_bounds__(256) void gemm_kernel(const float* __restrict__ E,
                                                   int nRows) {
    __shared__ float As[KC][68];   // [kk][row], rows 8B-aligned pairs
    __shared__ float Bs[KC][128];  // [kk][col]
    __shared__ float w1s[H], w2s[H];

    int t = threadIdx.x;
    int lane = t & 31;   // col group: cols [4*lane, 4*lane+4)
    int rg = t >> 5;     // warp id: rows [8*rg, 8*rg+8)
    int row0 = blockIdx.x * TM;

    if (t < H) { w1s[t] = d_w1[t]; w2s[t] = d_w2[t]; }

    unsigned long long acc[4][4];
#pragma unroll
    for (int p = 0; p < 4; p++)
#pragma unroll
        for (int c = 0; c < 4; c++) acc[p][c] = 0ull;

    float sA = 0.f, sB = 0.f;

    for (int k0 = 0; k0 < H; k0 += KC) {
        __syncthreads();
        // load A chunk: 64 rows x 32 k  (2 float4 per thread)
#pragma unroll
        for (int rep = 0; rep < 2; rep++) {
            int i = t + rep * 256;
            int r = i >> 3;            // 0..63
            int kq = (i & 7) * 4;      // 0..28
            int rm = row0 + r;
            if (rm > nRows - 1) rm = nRows - 1;
            float4 v = *(const float4*)&E[(size_t)rm * H + k0 + kq];
            As[kq + 0][r] = v.x;
            As[kq + 1][r] = v.y;
            As[kq + 2][r] = v.z;
            As[kq + 3][r] = v.w;
        }
        // load B chunk: 32 k x 128 cols (4 float4 per thread)
#pragma unroll
        for (int rep = 0; rep < 4; rep++) {
            int i = t + rep * 256;
            int kk = i >> 5;
            int c4 = (i & 31) * 4;
            *(float4*)&Bs[kk][c4] = *(const float4*)&d_M[(k0 + kk) * H + c4];
        }
        __syncthreads();

#pragma unroll
        for (int kk = 0; kk < KC; kk++) {
            const float* arow = &As[kk][rg * 8];
            unsigned long long ap[4];
#pragma unroll
            for (int p = 0; p < 4; p++)
                ap[p] = *(const unsigned long long*)(arow + 2 * p);
            float4 b = *(const float4*)&Bs[kk][lane * 4];
            unsigned long long b0 = pack2(b.x, b.x);
            unsigned long long b1 = pack2(b.y, b.y);
            unsigned long long b2 = pack2(b.z, b.z);
            unsigned long long b3 = pack2(b.w, b.w);
#pragma unroll
            for (int p = 0; p < 4; p++) {
                ffma2(acc[p][0], ap[p], b0);
                ffma2(acc[p][1], ap[p], b1);
                ffma2(acc[p][2], ap[p], b2);
                ffma2(acc[p][3], ap[p], b3);
            }
        }
        // score-path dot products (one thread per tile row)
        if (t < TM) {
#pragma unroll
            for (int kk = 0; kk < KC; kk++) {
                float av = As[kk][t];
                sA += av * w1s[k0 + kk];
                sB += av * w2s[k0 + kk];
            }
        }
    }

#pragma unroll
    for (int p = 0; p < 4; p++) {
        float2 c0 = unpack2(acc[p][0]);
        float2 c1 = unpack2(acc[p][1]);
        float2 c2 = unpack2(acc[p][2]);
        float2 c3 = unpack2(acc[p][3]);
        size_t r = (size_t)row0 + rg * 8 + 2 * p;
        float4 lo = make_float4(c0.x, c1.x, c2.x, c3.x);
        float4 hi = make_float4(c0.y, c1.y, c2.y, c3.y);
        *(float4*)&d_g[r * H + lane * 4] = lo;
        *(float4*)&d_g[(r + 1) * H + lane * 4] = hi;
    }
    if (t < TM) {
        d_ssrc[row0 + t] = sA;
        d_sdst[row0 + t] = sB;
    }
}

// ---------------- attention: score, rank-based top-k, softmax, gather --------
// one warp per entity; lane d owns candidate d (DEG == 32).
__global__ __launch_bounds__(256) void attn_kernel(const int* __restrict__ src,
                                                   const int* __restrict__ rel,
                                                   float* __restrict__ out,
                                                   int nEnt) {
    int gwarp = (blockIdx.x * blockDim.x + threadIdx.x) >> 5;
    int lane = threadIdx.x & 31;
    if (gwarp >= nEnt) return;
    int n = gwarp;

    int s = src[(size_t)n * DEG + lane];
    int r = rel[(size_t)n * DEG + lane];
    float sc = d_ssrc[s] + d_sdst[n] + d_srel[r];
    sc = sc >= 0.f ? sc : 0.2f * sc;  // leaky_relu(0.2)

    // rank of this lane's score under total order (score desc, lane asc).
    // Matches lax.top_k exactly: ties resolved to the lowest index.
    int rank = 0;
#pragma unroll
    for (int o = 1; o < 32; o++) {
        int j = (lane + o) & 31;
        float ov = __shfl_sync(0xffffffffu, sc, j);
        rank += (ov > sc) || (ov == sc && j < lane);
    }

    // softmax over the 10 selected lanes (global max == rank-0 score)
    float m = sc;
#pragma unroll
    for (int o = 16; o > 0; o >>= 1)
        m = fmaxf(m, __shfl_xor_sync(0xffffffffu, m, o));

    float e = (rank < TOPK) ? __expf(sc - m) : 0.f;
    float denom = e;
#pragma unroll
    for (int o = 16; o > 0; o >>= 1)
        denom += __shfl_xor_sync(0xffffffffu, denom, o);
    float inv = __fdividef(1.0f, denom);

    unsigned mask = __ballot_sync(0xffffffffu, rank < TOPK);

    // gather + unnormalized weighted sum: lane owns 4 feature channels
    float4 acc = make_float4(0.f, 0.f, 0.f, 0.f);
#pragma unroll
    for (int k = 0; k < TOPK; k++) {
        int l = __ffs(mask) - 1;
        mask &= mask - 1;
        int sk = __shfl_sync(0xffffffffu, s, l);
        int rk = __shfl_sync(0xffffffffu, r, l);
        float wk = __shfl_sync(0xffffffffu, e, l);
        float4 gv = *(const float4*)&d_g[(size_t)sk * H + lane * 4];
        float4 rv = *(const float4*)&d_grel[(size_t)rk * H + lane * 4];
        acc.x = fmaf(wk, gv.x + rv.x, acc.x);
        acc.y = fmaf(wk, gv.y + rv.y, acc.y);
        acc.z = fmaf(wk, gv.z + rv.z, acc.z);
        acc.w = fmaf(wk, gv.w + rv.w, acc.w);
    }
    float4 o4 = make_float4(tanhf(acc.x * inv), tanhf(acc.y * inv),
                            tanhf(acc.z * inv), tanhf(acc.w * inv));
    *(float4*)&out[(size_t)n * H + lane * 4] = o4;
}

// ---------------- launch -----------------------------------------------------
extern "C" void kernel_launch(void* const* d_in, const int* in_sizes, int n_in,
                              void* d_out, int out_size) {
    const float* ent = (const float*)d_in[0];   // [N, H]
    const float* rel = (const float*)d_in[1];   // [R, H]
    const float* W   = (const float*)d_in[2];   // [H, H]
    const float* Wr  = (const float*)d_in[3];   // [H, H]
    const float* a   = (const float*)d_in[4];   // [3H, 1]
    const float* NW  = (const float*)d_in[5];   // [H, H]
    const int* src   = (const int*)d_in[6];     // [N, DEG]
    const int* relid = (const int*)d_in[7];     // [N, DEG]
    float* out = (float*)d_out;                 // [N, H]

    int nEnt = in_sizes[0] / H;
    int nRel = in_sizes[1] / H;

    prep1_kernel<<<H, H>>>(W, Wr, a, NW);
    prep2_kernel<<<nRel, H>>>(rel);
    gemm_kernel<<<(nEnt + TM - 1) / TM, 256>>>(ent, nEnt);
    attn_kernel<<<((size_t)nEnt * 32 + 255) / 256, 256>>>(src, relid, out, nEnt);
}

// round 15
// speedup vs baseline: 1.2456x; 1.0889x over previous
#include <cuda_runtime.h>
#include <cuda_bf16.h>
#include <mma.h>
#include <cstdint>
#include <math.h>

using namespace nvcuda;

#define H 128
#define DEG 32
#define TOPK 10
#define NPAD 150016   // 150000 padded to 128*1172
#define RPAD 512
#define LDP 136       // padded k-stride (elements) for smem tiles; 272B = 17*16B

// ---------------- scratch (device globals; no allocation allowed) ------------
__device__ float d_Mr[H * H];       // W_r @ neigh_w
__device__ float d_w1[H];           // W @ a1
__device__ float d_w2[H];           // W @ a2
__device__ float d_w3[H];           // W_r @ a3
__device__ float d_srel[RPAD];      // rel_emb . w3
__device__ float d_grel[RPAD * H];  // rel_emb @ Mr
__device__ float d_g[(size_t)NPAD * H];  // ent_emb @ (W@neigh_w)
__device__ float d_ssrc[NPAD];
__device__ float d_sdst[NPAD];
// B = (W@neigh_w)^T as bf16 hi/lo, stored [n][k] padded to LDP (col_major for wmma)
__device__ __align__(16) __nv_bfloat16 d_Bhi[H * LDP];
__device__ __align__(16) __nv_bfloat16 d_Blo[H * LDP];

// ---------------- prep1: fold weights, emit bf16-split B ---------------------
__global__ void prep1_kernel(const float* __restrict__ W,
                             const float* __restrict__ Wr,
                             const float* __restrict__ a,
                             const float* __restrict__ NW) {
    int r = blockIdx.x;   // k index (row of M)
    int c = threadIdx.x;  // n index (col of M)
    float m = 0.f, mr = 0.f;
#pragma unroll 8
    for (int k = 0; k < H; k++) {
        float nw = NW[k * H + c];
        m  += W[r * H + k] * nw;
        mr += Wr[r * H + k] * nw;
    }
    d_Mr[r * H + c] = mr;
    // B[n][k] = M[k][n]; hi/lo bf16 split
    __nv_bfloat16 hi = __float2bfloat16(m);
    __nv_bfloat16 lo = __float2bfloat16(m - __bfloat162float(hi));
    d_Bhi[c * LDP + r] = hi;
    d_Blo[c * LDP + r] = lo;
    if (c == 0) {
        float s1 = 0.f, s2 = 0.f, s3 = 0.f;
        for (int j = 0; j < H; j++) {
            s1 += W[r * H + j] * a[j];
            s2 += W[r * H + j] * a[H + j];
            s3 += Wr[r * H + j] * a[2 * H + j];
        }
        d_w1[r] = s1;
        d_w2[r] = s2;
        d_w3[r] = s3;
    }
}

// ---------------- prep2: relation tables (fp32 exact) ------------------------
__global__ void prep2_kernel(const float* __restrict__ rel_emb) {
    int r = blockIdx.x;
    int c = threadIdx.x;
    __shared__ float re[H];
    re[c] = rel_emb[r * H + c];
    __syncthreads();
    float acc = 0.f;
#pragma unroll 8
    for (int k = 0; k < H; k++) acc += re[k] * d_Mr[k * H + c];
    d_grel[r * H + c] = acc;
    if (c == 0) {
        float s = 0.f;
        for (int i = 0; i < H; i++) s += re[i] * d_w3[i];
        d_srel[r] = s;
    }
}

// smem layout (dynamic), bytes
#define SM_AHI 0
#define SM_ALO (SM_AHI + H * LDP * 2)          // 34816
#define SM_BHI (SM_ALO + H * LDP * 2)
#define SM_BLO (SM_BHI + H * LDP * 2)
#define SM_W   (SM_BLO + H * LDP * 2)          // w1s, w2s
#define SM_TOTAL (SM_W + 2 * H * 4)

__device__ __forceinline__ uint16_t bfbits(float x) {
    __nv_bfloat16 h = __float2bfloat16(x);
    return *(uint16_t*)&h;
}

// ---------------- main GEMM: g = ent_emb @ M via wmma bf16 3-pass split ------
// 1 CTA = 128 rows x 128 cols, K = 128. 256 threads = 8 warps.
// warp tile: 32 rows x 64 cols (2x4 wmma 16x16 tiles).
__global__ __launch_bounds__(256, 1) void gemm_wmma_kernel(const float* __restrict__ E,
                                                           int nRows) {
    extern __shared__ char smem[];
    __nv_bfloat16* Ahi = (__nv_bfloat16*)(smem + SM_AHI);
    __nv_bfloat16* Alo = (__nv_bfloat16*)(smem + SM_ALO);
    __nv_bfloat16* Bhi = (__nv_bfloat16*)(smem + SM_BHI);
    __nv_bfloat16* Blo = (__nv_bfloat16*)(smem + SM_BLO);
    float* w1s = (float*)(smem + SM_W);
    float* w2s = w1s + H;

    int t = threadIdx.x;
    int wid = t >> 5;
    int row0 = blockIdx.x * 128;

    // stage B hi/lo into smem (17 float4 per n-row; 2176 float4 per tile)
    if (t < H) { w1s[t] = d_w1[t]; w2s[t] = d_w2[t]; }
    for (int i = t; i < H * LDP * 2 / 16; i += 256) {
        ((float4*)Bhi)[i] = ((const float4*)d_Bhi)[i];
        ((float4*)Blo)[i] = ((const float4*)d_Blo)[i];
    }
    __syncthreads();

    // load E tile, split to bf16 hi/lo, fuse exact fp32 score dots
    {
        int rowA = t >> 1;           // 0..127
        int half = t & 1;            // k-half: [0,64) or [64,128)
        int gr = row0 + rowA;
        if (gr > nRows - 1) gr = nRows - 1;
        const float4* Erow = (const float4*)&E[(size_t)gr * H + half * 64];
        float s1 = 0.f, s2 = 0.f;
#pragma unroll
        for (int q = 0; q < 16; q++) {
            float4 v = Erow[q];
            int k = half * 64 + q * 4;
            s1 += v.x * w1s[k] + v.y * w1s[k + 1] + v.z * w1s[k + 2] + v.w * w1s[k + 3];
            s2 += v.x * w2s[k] + v.y * w2s[k + 1] + v.z * w2s[k + 2] + v.w * w2s[k + 3];
            uint16_t hx = bfbits(v.x), hy = bfbits(v.y), hz = bfbits(v.z), hw = bfbits(v.w);
            float fx = __bfloat162float(*(__nv_bfloat16*)&hx);
            float fy = __bfloat162float(*(__nv_bfloat16*)&hy);
            float fz = __bfloat162float(*(__nv_bfloat16*)&hz);
            float fw = __bfloat162float(*(__nv_bfloat16*)&hw);
            uint16_t lx = bfbits(v.x - fx), ly = bfbits(v.y - fy);
            uint16_t lz = bfbits(v.z - fz), lw = bfbits(v.w - fw);
            uint32_t o = (uint32_t)rowA * LDP + k;   // element offset
            *(uint2*)(Ahi + o) =
                make_uint2((uint32_t)hx | ((uint32_t)hy << 16),
                           (uint32_t)hz | ((uint32_t)hw << 16));
            *(uint2*)(Alo + o) =
                make_uint2((uint32_t)lx | ((uint32_t)ly << 16),
                           (uint32_t)lz | ((uint32_t)lw << 16));
        }
        s1 += __shfl_xor_sync(0xffffffffu, s1, 1);
        s2 += __shfl_xor_sync(0xffffffffu, s2, 1);
        if (half == 0 && row0 + rowA < nRows) {
            d_ssrc[row0 + rowA] = s1;
            d_sdst[row0 + rowA] = s2;
        }
    }
    __syncthreads();

    // 3 passes: hi*hi, hi*lo, lo*hi — all into the same fp32 accumulators
    int wm = wid & 3;   // row group (32 rows)
    int wn = wid >> 2;  // col group (64 cols)

    wmma::fragment<wmma::accumulator, 16, 16, 16, float> c[2][4];
#pragma unroll
    for (int i = 0; i < 2; i++)
#pragma unroll
        for (int j = 0; j < 4; j++) wmma::fill_fragment(c[i][j], 0.f);

    const __nv_bfloat16* pa[3] = {Ahi, Ahi, Alo};
    const __nv_bfloat16* pb[3] = {Bhi, Blo, Bhi};

#pragma unroll
    for (int p = 0; p < 3; p++) {
        const __nv_bfloat16* A = pa[p];
        const __nv_bfloat16* B = pb[p];
#pragma unroll
        for (int ks = 0; ks < 8; ks++) {
            wmma::fragment<wmma::matrix_a, 16, 16, 16, __nv_bfloat16, wmma::row_major> af[2];
#pragma unroll
            for (int i = 0; i < 2; i++)
                wmma::load_matrix_sync(af[i], A + (wm * 32 + i * 16) * LDP + ks * 16, LDP);
            wmma::fragment<wmma::matrix_b, 16, 16, 16, __nv_bfloat16, wmma::col_major> bf[4];
#pragma unroll
            for (int j = 0; j < 4; j++)
                wmma::load_matrix_sync(bf[j], B + (wn * 64 + j * 16) * LDP + ks * 16, LDP);
#pragma unroll
            for (int i = 0; i < 2; i++)
#pragma unroll
                for (int j = 0; j < 4; j++)
                    wmma::mma_sync(c[i][j], af[i], bf[j], c[i][j]);
        }
    }

    // store accumulators directly to d_g (rows padded to NPAD, no OOB)
#pragma unroll
    for (int i = 0; i < 2; i++)
#pragma unroll
        for (int j = 0; j < 4; j++) {
            size_t r = (size_t)(row0 + wm * 32 + i * 16);
            wmma::store_matrix_sync(&d_g[r * H + wn * 64 + j * 16], c[i][j], H,
                                    wmma::mem_row_major);
        }
}

// ---------------- attention: score, rank-based top-k, softmax, gather --------
__global__ __launch_bounds__(256) void attn_kernel(const int* __restrict__ src,
                                                   const int* __restrict__ rel,
                                                   float* __restrict__ out,
                                                   int nEnt) {
    int gwarp = (blockIdx.x * blockDim.x + threadIdx.x) >> 5;
    int lane = threadIdx.x & 31;
    if (gwarp >= nEnt) return;
    int n = gwarp;

    int s = src[(size_t)n * DEG + lane];
    int r = rel[(size_t)n * DEG + lane];
    float sc = d_ssrc[s] + d_sdst[n] + d_srel[r];
    sc = sc >= 0.f ? sc : 0.2f * sc;  // leaky_relu(0.2)

    // rank under total order (score desc, lane asc) == lax.top_k tie rule
    int rank = 0;
#pragma unroll
    for (int o = 1; o < 32; o++) {
        int j = (lane + o) & 31;
        float ov = __shfl_sync(0xffffffffu, sc, j);
        rank += (ov > sc) || (ov == sc && j < lane);
    }

    float m = sc;
#pragma unroll
    for (int o = 16; o > 0; o >>= 1)
        m = fmaxf(m, __shfl_xor_sync(0xffffffffu, m, o));

    float e = (rank < TOPK) ? __expf(sc - m) : 0.f;
    float denom = e;
#pragma unroll
    for (int o = 16; o > 0; o >>= 1)
        denom += __shfl_xor_sync(0xffffffffu, denom, o);
    float inv = __fdividef(1.0f, denom);

    unsigned mask = __ballot_sync(0xffffffffu, rank < TOPK);

    float4 acc = make_float4(0.f, 0.f, 0.f, 0.f);
#pragma unroll
    for (int k = 0; k < TOPK; k++) {
        int l = __ffs(mask) - 1;
        mask &= mask - 1;
        int sk = __shfl_sync(0xffffffffu, s, l);
        int rk = __shfl_sync(0xffffffffu, r, l);
        float wk = __shfl_sync(0xffffffffu, e, l);
        float4 gv = *(const float4*)&d_g[(size_t)sk * H + lane * 4];
        float4 rv = *(const float4*)&d_grel[(size_t)rk * H + lane * 4];
        acc.x = fmaf(wk, gv.x + rv.x, acc.x);
        acc.y = fmaf(wk, gv.y + rv.y, acc.y);
        acc.z = fmaf(wk, gv.z + rv.z, acc.z);
        acc.w = fmaf(wk, gv.w + rv.w, acc.w);
    }
    float4 o4 = make_float4(tanhf(acc.x * inv), tanhf(acc.y * inv),
                            tanhf(acc.z * inv), tanhf(acc.w * inv));
    *(float4*)&out[(size_t)n * H + lane * 4] = o4;
}

// ---------------- launch -----------------------------------------------------
extern "C" void kernel_launch(void* const* d_in, const int* in_sizes, int n_in,
                              void* d_out, int out_size) {
    const float* ent = (const float*)d_in[0];   // [N, H]
    const float* rel = (const float*)d_in[1];   // [R, H]
    const float* W   = (const float*)d_in[2];   // [H, H]
    const float* Wr  = (const float*)d_in[3];   // [H, H]
    const float* a   = (const float*)d_in[4];   // [3H, 1]
    const float* NW  = (const float*)d_in[5];   // [H, H]
    const int* src   = (const int*)d_in[6];     // [N, DEG]
    const int* relid = (const int*)d_in[7];     // [N, DEG]
    float* out = (float*)d_out;                 // [N, H]

    int nEnt = in_sizes[0] / H;
    int nRel = in_sizes[1] / H;

    cudaFuncSetAttribute(gemm_wmma_kernel,
                         cudaFuncAttributeMaxDynamicSharedMemorySize, SM_TOTAL);

    prep1_kernel<<<H, H>>>(W, Wr, a, NW);
    prep2_kernel<<<nRel, H>>>(rel);
    gemm_wmma_kernel<<<(nEnt + 127) / 128, 256, SM_TOTAL>>>(ent, nEnt);
    attn_kernel<<<((size_t)nEnt * 32 + 255) / 256, 256>>>(src, relid, out, nEnt);
}